// round 1
// baseline (speedup 1.0000x reference)
#include <cuda_runtime.h>
#include <cuda_bf16.h>
#include <cstdint>

#define Bq 2
#define Dq 128
#define Hq 128
#define Wq 128
#define Nq 400000
#define Kq 27
#define Cq 64
#define EPSq 1e-5f

#define TABLE_SIZE (Bq * Dq * Hq * Wq)   // 4,194,304

// ---- scratch (allocation-free rule: device globals) ----
__device__ int   g_table[TABLE_SIZE];        // voxel hash table (dense grid)
__device__ int   g_nbr[Kq * Nq];             // rulebook, k-major
__device__ float g_xa[(size_t)Nq * Cq];      // activations ping
__device__ float g_xb[(size_t)Nq * Cq];      // activations pong

// ---------------------------------------------------------------------------
// Rulebook construction
// ---------------------------------------------------------------------------
__global__ void init_table_kernel() {
    int i = blockIdx.x * blockDim.x + threadIdx.x;
    int stride = gridDim.x * blockDim.x;
    for (; i < TABLE_SIZE; i += stride) g_table[i] = -1;
}

__global__ void scatter_kernel(const int* __restrict__ coords) {
    int i = blockIdx.x * blockDim.x + threadIdx.x;
    if (i >= Nq) return;
    int b = coords[i * 4 + 0];
    int z = coords[i * 4 + 1];
    int y = coords[i * 4 + 2];
    int x = coords[i * 4 + 3];
    int flat = ((b * Dq + z) * Hq + y) * Wq + x;
    g_table[flat] = i;
}

__global__ void build_nbr_kernel(const int* __restrict__ coords) {
    int i = blockIdx.x * blockDim.x + threadIdx.x;
    if (i >= Nq) return;
    int b = coords[i * 4 + 0];
    int z = coords[i * 4 + 1];
    int y = coords[i * 4 + 2];
    int x = coords[i * 4 + 3];
    int base = b * Dq;
    #pragma unroll
    for (int k = 0; k < Kq; k++) {
        int dz = k / 9 - 1;
        int dy = (k / 3) % 3 - 1;
        int dx = k % 3 - 1;
        int nz = z + dz, ny = y + dy, nx = x + dx;
        int r = -1;
        if (nz >= 0 && nz < Dq && ny >= 0 && ny < Hq && nx >= 0 && nx < Wq) {
            int flat = ((base + nz) * Hq + ny) * Wq + nx;
            r = g_table[flat];
        }
        g_nbr[k * Nq + i] = r;
    }
}

// ---------------------------------------------------------------------------
// Layer 1: cin = 1  (per voxel: 27 scalar gathers, 27 FMAs per out channel)
// blockDim = 256, TILE = 64 voxels. thread: c = t&63, vgroup = t>>6 (16 vox ea)
// ---------------------------------------------------------------------------
__global__ void __launch_bounds__(256) layer1_kernel(
    const float* __restrict__ feats,
    const float* __restrict__ w,      // [27,1,64]
    const float* __restrict__ bias,
    const float* __restrict__ gg, const float* __restrict__ be,
    const float* __restrict__ mm, const float* __restrict__ vv,
    float* __restrict__ xout)
{
    __shared__ float s_w[Kq * Cq];        // 27*64
    __shared__ float s_f[64][Kq];         // 64 voxels x 27 taps
    const int tid = threadIdx.x;
    const int v0 = blockIdx.x * 64;

    for (int i = tid; i < Kq * Cq; i += 256) s_w[i] = w[i];

    for (int idx = tid; idx < 64 * Kq; idx += 256) {
        int v = idx / Kq, k = idx % Kq;
        int n = g_nbr[k * Nq + v0 + v];
        s_f[v][k] = (n >= 0) ? feats[n] : 0.f;
    }
    __syncthreads();

    const int c  = tid & 63;
    const int vg = tid >> 6;
    const float sc = gg[c] * rsqrtf(vv[c] + EPSq);
    const float sh = be[c] - mm[c] * sc;
    const float bc = bias[c];

    #pragma unroll
    for (int i = 0; i < 16; i++) {
        int v = vg * 16 + i;
        float acc = bc;
        #pragma unroll
        for (int k = 0; k < Kq; k++) acc += s_f[v][k] * s_w[k * Cq + c];
        float r = fmaxf(acc * sc + sh, 0.f);
        xout[(size_t)(v0 + v) * Cq + c] = r;
    }
}

// ---------------------------------------------------------------------------
// Layers 2/3: cin = cout = 64. Tile: 32 voxels/block, blockDim 256.
// thread: c = t&63, vg = t>>6; each vg owns 8 voxels (register accumulators).
// Per kernel offset k: stage w[k] (16KB) + 32 gathered feature rows (8KB) to
// smem, then 32-voxel x 64x64 mini-GEMM. Inner loop: 12 LDS : 32 FMA.
// ---------------------------------------------------------------------------
__global__ void __launch_bounds__(256) conv64_kernel(
    const float* __restrict__ xin,
    const float* __restrict__ w,      // [27,64,64]
    const float* __restrict__ bias,
    const float* __restrict__ gg, const float* __restrict__ be,
    const float* __restrict__ mm, const float* __restrict__ vv,
    float* __restrict__ xout)
{
    __shared__ __align__(16) float s_w[Cq * Cq];     // 16 KB
    __shared__ __align__(16) float s_f[32][Cq];      // 8 KB
    __shared__ int s_nbr[32];

    const int tid = threadIdx.x;
    const int v0  = blockIdx.x * 32;
    const int c   = tid & 63;
    const int vg  = tid >> 6;

    float acc[8];
    const float bc = __ldg(&bias[c]);
    #pragma unroll
    for (int i = 0; i < 8; i++) acc[i] = bc;

    for (int k = 0; k < Kq; k++) {
        __syncthreads();   // previous compute done before smem overwrite
        // stage weights: 4096 floats = 1024 float4
        const float4* wk = (const float4*)(w + k * Cq * Cq);
        float4* swv = (float4*)s_w;
        #pragma unroll
        for (int r = 0; r < 4; r++) swv[tid + 256 * r] = wk[tid + 256 * r];
        if (tid < 32) s_nbr[tid] = g_nbr[k * Nq + v0 + tid];
        __syncthreads();
        // gather 32 feature rows: 512 float4, 2 per thread
        #pragma unroll
        for (int r = 0; r < 2; r++) {
            int idx = tid + 256 * r;
            int v  = idx >> 4;
            int j4 = idx & 15;
            int n = s_nbr[v];
            float4 f = make_float4(0.f, 0.f, 0.f, 0.f);
            if (n >= 0) f = ((const float4*)(xin + (size_t)n * Cq))[j4];
            ((float4*)&s_f[v][0])[j4] = f;
        }
        __syncthreads();
        // mini-GEMM
        #pragma unroll
        for (int j4 = 0; j4 < 16; j4++) {
            float w0 = s_w[(4 * j4 + 0) * Cq + c];
            float w1 = s_w[(4 * j4 + 1) * Cq + c];
            float w2 = s_w[(4 * j4 + 2) * Cq + c];
            float w3 = s_w[(4 * j4 + 3) * Cq + c];
            #pragma unroll
            for (int i = 0; i < 8; i++) {
                float4 f = ((const float4*)&s_f[vg * 8 + i][0])[j4];
                acc[i] += f.x * w0;
                acc[i] += f.y * w1;
                acc[i] += f.z * w2;
                acc[i] += f.w * w3;
            }
        }
    }

    const float sc = gg[c] * rsqrtf(vv[c] + EPSq);
    const float sh = be[c] - mm[c] * sc;
    #pragma unroll
    for (int i = 0; i < 8; i++) {
        int v = v0 + vg * 8 + i;
        float r = fmaxf(acc[i] * sc + sh, 0.f);
        xout[(size_t)v * Cq + c] = r;
    }
}

// ---------------------------------------------------------------------------
extern "C" void kernel_launch(void* const* d_in, const int* in_sizes, int n_in,
                              void* d_out, int out_size)
{
    const float* feats  = (const float*)d_in[0];
    const int*   coords = (const int*)  d_in[1];
    // layer param order: w,b,g,be,m,v  per layer
    const float* w1 = (const float*)d_in[2];
    const float* b1 = (const float*)d_in[3];
    const float* g1 = (const float*)d_in[4];
    const float* be1= (const float*)d_in[5];
    const float* m1 = (const float*)d_in[6];
    const float* v1 = (const float*)d_in[7];
    const float* w2 = (const float*)d_in[8];
    const float* b2 = (const float*)d_in[9];
    const float* g2 = (const float*)d_in[10];
    const float* be2= (const float*)d_in[11];
    const float* m2 = (const float*)d_in[12];
    const float* v2 = (const float*)d_in[13];
    const float* w3 = (const float*)d_in[14];
    const float* b3 = (const float*)d_in[15];
    const float* g3 = (const float*)d_in[16];
    const float* be3= (const float*)d_in[17];
    const float* m3 = (const float*)d_in[18];
    const float* v3 = (const float*)d_in[19];
    float* out = (float*)d_out;

    // rulebook
    init_table_kernel<<<1024, 256>>>();
    scatter_kernel<<<(Nq + 255) / 256, 256>>>(coords);
    build_nbr_kernel<<<(Nq + 255) / 256, 256>>>(coords);

    // layer 1: feats -> g_xa
    layer1_kernel<<<Nq / 64, 256>>>(feats, w1, b1, g1, be1, m1, v1, g_xa);
    // layer 2: g_xa -> g_xb
    conv64_kernel<<<Nq / 32, 256>>>(g_xa, w2, b2, g2, be2, m2, v2, g_xb);
    // layer 3: g_xb -> out
    conv64_kernel<<<Nq / 32, 256>>>(g_xb, w3, b3, g3, be3, m3, v3, out);
}

// round 3
// speedup vs baseline: 4.3570x; 4.3570x over previous
#include <cuda_runtime.h>
#include <cuda_bf16.h>
#include <cstdint>

#define Nq 400000
#define Kq 27
#define Cq 64
#define Dq 128
#define Hq 128
#define Wq 128
#define EPSq 1e-5f
#define TABLE_SIZE (2 * Dq * Hq * Wq)   // 4,194,304

// ---- scratch (device globals; allocation-free rule) ----
__device__ int   g_table[TABLE_SIZE];
__device__ int   g_nbr[Kq * Nq];
// activations as bf16 hi/lo pairs (precision doubling)
__device__ __nv_bfloat16 g_h1[(size_t)Nq * Cq];
__device__ __nv_bfloat16 g_l1[(size_t)Nq * Cq];
__device__ __nv_bfloat16 g_h2[(size_t)Nq * Cq];
__device__ __nv_bfloat16 g_l2[(size_t)Nq * Cq];
// pre-packed B fragments: [k][part(hi/lo)][kc(4)][n8(8)][lane(32)] x uint2
__device__ uint2 g_wf2[Kq * 2048];
__device__ uint2 g_wf3[Kq * 2048];

// ---------------------------------------------------------------------------
// helpers
// ---------------------------------------------------------------------------
__device__ __forceinline__ uint32_t smem_u32(const void* p) {
    uint32_t a;
    asm("{ .reg .u64 t; cvta.to.shared.u64 t, %1; cvt.u32.u64 %0, t; }" : "=r"(a) : "l"(p));
    return a;
}

__device__ __forceinline__ void mma_bf16(float* d, const uint32_t* a, uint32_t b0, uint32_t b1) {
    asm volatile(
        "mma.sync.aligned.m16n8k16.row.col.f32.bf16.bf16.f32 "
        "{%0,%1,%2,%3}, {%4,%5,%6,%7}, {%8,%9}, {%0,%1,%2,%3};"
        : "+f"(d[0]), "+f"(d[1]), "+f"(d[2]), "+f"(d[3])
        : "r"(a[0]), "r"(a[1]), "r"(a[2]), "r"(a[3]), "r"(b0), "r"(b1));
}

__device__ __forceinline__ void ldm_x4(uint32_t* a, uint32_t addr) {
    asm volatile(
        "ldmatrix.sync.aligned.m8n8.x4.shared.b16 {%0,%1,%2,%3}, [%4];"
        : "=r"(a[0]), "=r"(a[1]), "=r"(a[2]), "=r"(a[3]) : "r"(addr));
}

__device__ __forceinline__ void cp16(uint32_t dst, const void* src, uint32_t srcsize) {
    asm volatile("cp.async.cg.shared.global [%0], [%1], 16, %2;"
                 :: "r"(dst), "l"(src), "r"(srcsize) : "memory");
}
__device__ __forceinline__ void cp_commit() {
    asm volatile("cp.async.commit_group;" ::: "memory");
}

// ---------------------------------------------------------------------------
// rulebook
// ---------------------------------------------------------------------------
__global__ void init_table_kernel() {
    int i = blockIdx.x * blockDim.x + threadIdx.x;
    ((int4*)g_table)[i] = make_int4(-1, -1, -1, -1);
}

__global__ void scatter_kernel(const int* __restrict__ coords) {
    int i = blockIdx.x * blockDim.x + threadIdx.x;
    if (i >= Nq) return;
    int b = coords[i * 4 + 0], z = coords[i * 4 + 1];
    int y = coords[i * 4 + 2], x = coords[i * 4 + 3];
    g_table[((b * Dq + z) * Hq + y) * Wq + x] = i;
}

__global__ void build_nbr_kernel(const int* __restrict__ coords) {
    int i = blockIdx.x * blockDim.x + threadIdx.x;
    if (i >= Nq) return;
    int b = coords[i * 4 + 0], z = coords[i * 4 + 1];
    int y = coords[i * 4 + 2], x = coords[i * 4 + 3];
    #pragma unroll
    for (int k = 0; k < Kq; k++) {
        int dz = k / 9 - 1, dy = (k / 3) % 3 - 1, dx = k % 3 - 1;
        int nz = z + dz, ny = y + dy, nx = x + dx;
        int r = -1;
        if (nz >= 0 && nz < Dq && ny >= 0 && ny < Hq && nx >= 0 && nx < Wq)
            r = g_table[((b * Dq + nz) * Hq + ny) * Wq + nx];
        g_nbr[k * Nq + i] = r;
    }
}

// ---------------------------------------------------------------------------
// weight prep: w[k][cin][cout] fp32 -> per-thread mma B fragments, bf16 hi/lo
// B frag (m16n8k16, col): b0 = {B[kl][n], B[kl+1][n]}, b1 = {B[kl+8][n], B[kl+9][n]}
//   n = n8*8 + lane/4, kl = (lane%4)*2, cin = kc*16 + kl
// ---------------------------------------------------------------------------
__global__ void prep_w_kernel(const float* __restrict__ w, uint2* __restrict__ frag) {
    int idx = blockIdx.x * blockDim.x + threadIdx.x;
    if (idx >= Kq * 2048) return;
    int lane = idx & 31;
    int n8   = (idx >> 5) & 7;
    int kc   = (idx >> 8) & 3;
    int part = (idx >> 10) & 1;
    int k    = idx >> 11;

    int n  = n8 * 8 + (lane >> 2);
    int c0 = kc * 16 + (lane & 3) * 2;
    uint32_t r[2];
    #pragma unroll
    for (int h = 0; h < 2; h++) {                // h=0 -> b0 (rows c0,c0+1), h=1 -> b1 (+8)
        uint32_t packed = 0;
        #pragma unroll
        for (int e = 0; e < 2; e++) {
            float x = w[(k * 64 + (c0 + h * 8 + e)) * 64 + n];
            __nv_bfloat16 hi = __float2bfloat16_rn(x);
            __nv_bfloat16 val = part == 0 ? hi
                                : __float2bfloat16_rn(x - __bfloat162float(hi));
            uint16_t bits = *(uint16_t*)&val;
            packed |= (uint32_t)bits << (16 * e);
        }
        r[h] = packed;
    }
    frag[idx] = make_uint2(r[0], r[1]);
}

// ---------------------------------------------------------------------------
// layer 1 (cin=1): 128-voxel tiles, 256 threads, writes bf16 hi/lo
// ---------------------------------------------------------------------------
__global__ void __launch_bounds__(256) layer1_kernel(
    const float* __restrict__ feats, const float* __restrict__ w,
    const float* __restrict__ bias,
    const float* __restrict__ gg, const float* __restrict__ be,
    const float* __restrict__ mm, const float* __restrict__ vv,
    __nv_bfloat16* __restrict__ oh, __nv_bfloat16* __restrict__ ol)
{
    __shared__ float s_w[Kq * Cq];
    __shared__ float s_f[Kq * 128];
    __shared__ float s_scale[Cq], s_shift[Cq];

    const int tid = threadIdx.x;
    const int v0  = blockIdx.x * 128;

    if (tid < Cq) {
        float sc = gg[tid] * rsqrtf(vv[tid] + EPSq);
        s_scale[tid] = sc;
        s_shift[tid] = (bias[tid] - mm[tid]) * sc + be[tid];
    }
    for (int i = tid; i < Kq * Cq; i += 256) s_w[i] = w[i];

    #pragma unroll 7
    for (int idx = tid; idx < Kq * 128; idx += 256) {
        int k = idx >> 7, v = idx & 127;
        int n = g_nbr[k * Nq + v0 + v];
        s_f[idx] = (n >= 0) ? feats[n] : 0.f;
    }
    __syncthreads();

    const int c  = tid & 63;
    const int vg = tid >> 6;
    float acc[32];
    #pragma unroll
    for (int i = 0; i < 32; i++) acc[i] = 0.f;

    for (int k = 0; k < Kq; k++) {
        float wk = s_w[k * Cq + c];
        const float* fp = &s_f[k * 128 + vg * 32];
        #pragma unroll
        for (int i = 0; i < 32; i++) acc[i] = fmaf(fp[i], wk, acc[i]);
    }
    const float sc = s_scale[c], sh = s_shift[c];
    #pragma unroll
    for (int i = 0; i < 32; i++) {
        float r = fmaxf(fmaf(acc[i], sc, sh), 0.f);
        size_t o = (size_t)(v0 + vg * 32 + i) * Cq + c;
        __nv_bfloat16 hi = __float2bfloat16_rn(r);
        oh[o] = hi;
        ol[o] = __float2bfloat16_rn(r - __bfloat162float(hi));
    }
}

// ---------------------------------------------------------------------------
// conv64 via mma.sync bf16x3. 128 voxels/CTA, 256 threads (8 warps x 16 vox).
// smem: A tiles [2 buf][2 part][128 rows][128B swizzled]  = 64KB
//       B frag blob [2 buf][16KB]                          = 32KB
// ---------------------------------------------------------------------------
#define SM_A    0
#define SM_B    65536
#define SM_SCL  (SM_B + 32768)
#define SM_SFT  (SM_SCL + 256)
#define SM_TOT  (SM_SFT + 256)

__device__ __forceinline__ void stage_offset(
    int kk, int buf, int v0, int tid, uint32_t sbase,
    const __nv_bfloat16* __restrict__ xh, const __nv_bfloat16* __restrict__ xl,
    const uint2* __restrict__ wfrag)
{
    // gather 128 rows x (hi,lo) : thread -> (row = tid&127, part = tid>>7)
    int row  = tid & 127;
    int part = tid >> 7;
    int n = __ldg(&g_nbr[kk * Nq + v0 + row]);
    const __nv_bfloat16* src = (part ? xl : xh) + (size_t)(n < 0 ? 0 : n) * Cq;
    uint32_t srcsz = (n >= 0) ? 16u : 0u;
    uint32_t dbase = sbase + SM_A + buf * 32768 + part * 16384 + row * 128;
    uint32_t swz = (row & 7) << 4;
    #pragma unroll
    for (int j = 0; j < 8; j++)
        cp16(dbase + (((uint32_t)(j << 4)) ^ swz), src + j * 8, srcsz);
    // B fragment blob: 16KB for this offset
    const char* wsrc = (const char*)(wfrag + kk * 2048) + tid * 64;
    uint32_t wdst = sbase + SM_B + buf * 16384 + tid * 64;
    #pragma unroll
    for (int j = 0; j < 4; j++)
        cp16(wdst + j * 16, wsrc + j * 16, 16u);
}

__global__ void __launch_bounds__(256, 1) conv_mma_kernel(
    const __nv_bfloat16* __restrict__ xh, const __nv_bfloat16* __restrict__ xl,
    const uint2* __restrict__ wfrag,
    const float* __restrict__ bias,
    const float* __restrict__ gg, const float* __restrict__ be,
    const float* __restrict__ mm, const float* __restrict__ vv,
    float* __restrict__ out_f32,
    __nv_bfloat16* __restrict__ oh, __nv_bfloat16* __restrict__ ol,
    int outmode)
{
    extern __shared__ char smc[];
    const uint32_t sbase = smem_u32(smc);
    const int tid  = threadIdx.x;
    const int lane = tid & 31;
    const int warp = tid >> 5;
    const int v0   = blockIdx.x * 128;

    float* s_scale = (float*)(smc + SM_SCL);
    float* s_shift = (float*)(smc + SM_SFT);
    if (tid < Cq) {
        float sc = gg[tid] * rsqrtf(vv[tid] + EPSq);
        s_scale[tid] = sc;
        s_shift[tid] = (bias[tid] - mm[tid]) * sc + be[tid];
    }

    stage_offset(0, 0, v0, tid, sbase, xh, xl, wfrag);
    cp_commit();
    stage_offset(1, 1, v0, tid, sbase, xh, xl, wfrag);
    cp_commit();

    float d[8][4];
    #pragma unroll
    for (int i = 0; i < 8; i++)
        #pragma unroll
        for (int j = 0; j < 4; j++) d[i][j] = 0.f;

    // per-thread ldmatrix source address pieces
    const int rowl = (lane & 7) | (lane & 8);          // 0..15
    const int row  = warp * 16 + rowl;
    const uint32_t rbase = row * 128;
    const uint32_t swz   = (row & 7) << 4;
    const uint32_t colh  = (lane & 16);                // 0 or 16 bytes

    for (int k = 0; k < Kq; k++) {
        const int buf = k & 1;
        if (k == Kq - 1) asm volatile("cp.async.wait_group 0;" ::: "memory");
        else             asm volatile("cp.async.wait_group 1;" ::: "memory");
        __syncthreads();

        const uint32_t sa = sbase + SM_A + buf * 32768 + rbase;
        const uint2* sb = (const uint2*)(smc + SM_B + buf * 16384);

        #pragma unroll
        for (int kc = 0; kc < 4; kc++) {
            uint32_t boff = ((uint32_t)((kc << 5) | colh)) ^ swz;
            uint32_t ahi[4], alo[4];
            ldm_x4(ahi, sa + boff);
            ldm_x4(alo, sa + boff + 16384);
            #pragma unroll
            for (int n8 = 0; n8 < 8; n8++) {
                uint2 bh = sb[(kc * 8 + n8) * 32 + lane];
                uint2 bl = sb[((4 + kc) * 8 + n8) * 32 + lane];
                mma_bf16(d[n8], ahi, bh.x, bh.y);
                mma_bf16(d[n8], alo, bh.x, bh.y);
                mma_bf16(d[n8], ahi, bl.x, bl.y);
            }
        }
        __syncthreads();
        if (k < Kq - 2) {
            stage_offset(k + 2, buf, v0, tid, sbase, xh, xl, wfrag);
            cp_commit();
        }
    }

    // epilogue: BN + ReLU, write
    const int r0 = v0 + warp * 16 + (lane >> 2);
    const int r1 = r0 + 8;
    #pragma unroll
    for (int n8 = 0; n8 < 8; n8++) {
        int col = n8 * 8 + (lane & 3) * 2;
        float sc0 = s_scale[col], sc1 = s_scale[col + 1];
        float sh0 = s_shift[col], sh1 = s_shift[col + 1];
        float o00 = fmaxf(fmaf(d[n8][0], sc0, sh0), 0.f);
        float o01 = fmaxf(fmaf(d[n8][1], sc1, sh1), 0.f);
        float o10 = fmaxf(fmaf(d[n8][2], sc0, sh0), 0.f);
        float o11 = fmaxf(fmaf(d[n8][3], sc1, sh1), 0.f);
        if (outmode == 0) {
            *(float2*)(out_f32 + (size_t)r0 * Cq + col) = make_float2(o00, o01);
            *(float2*)(out_f32 + (size_t)r1 * Cq + col) = make_float2(o10, o11);
        } else {
            __nv_bfloat16 h00 = __float2bfloat16_rn(o00);
            __nv_bfloat16 h01 = __float2bfloat16_rn(o01);
            __nv_bfloat16 h10 = __float2bfloat16_rn(o10);
            __nv_bfloat16 h11 = __float2bfloat16_rn(o11);
            __nv_bfloat162 hv0; hv0.x = h00; hv0.y = h01;
            __nv_bfloat162 hv1; hv1.x = h10; hv1.y = h11;
            *(__nv_bfloat162*)(oh + (size_t)r0 * Cq + col) = hv0;
            *(__nv_bfloat162*)(oh + (size_t)r1 * Cq + col) = hv1;
            __nv_bfloat162 lv0, lv1;
            lv0.x = __float2bfloat16_rn(o00 - __bfloat162float(h00));
            lv0.y = __float2bfloat16_rn(o01 - __bfloat162float(h01));
            lv1.x = __float2bfloat16_rn(o10 - __bfloat162float(h10));
            lv1.y = __float2bfloat16_rn(o11 - __bfloat162float(h11));
            *(__nv_bfloat162*)(ol + (size_t)r0 * Cq + col) = lv0;
            *(__nv_bfloat162*)(ol + (size_t)r1 * Cq + col) = lv1;
        }
    }
}

// ---------------------------------------------------------------------------
extern "C" void kernel_launch(void* const* d_in, const int* in_sizes, int n_in,
                              void* d_out, int out_size)
{
    const float* feats  = (const float*)d_in[0];
    const int*   coords = (const int*)  d_in[1];
    const float* w1 = (const float*)d_in[2];
    const float* b1 = (const float*)d_in[3];
    const float* g1 = (const float*)d_in[4];
    const float* be1= (const float*)d_in[5];
    const float* m1 = (const float*)d_in[6];
    const float* v1 = (const float*)d_in[7];
    const float* w2 = (const float*)d_in[8];
    const float* b2 = (const float*)d_in[9];
    const float* g2 = (const float*)d_in[10];
    const float* be2= (const float*)d_in[11];
    const float* m2 = (const float*)d_in[12];
    const float* v2 = (const float*)d_in[13];
    const float* w3 = (const float*)d_in[14];
    const float* b3 = (const float*)d_in[15];
    const float* g3 = (const float*)d_in[16];
    const float* be3= (const float*)d_in[17];
    const float* m3 = (const float*)d_in[18];
    const float* v3 = (const float*)d_in[19];
    float* out = (float*)d_out;

    static bool attr_set = false;
    if (!attr_set) {
        cudaFuncSetAttribute(conv_mma_kernel,
                             cudaFuncAttributeMaxDynamicSharedMemorySize, SM_TOT);
        attr_set = true;
    }

    uint2 *wf2, *wf3;
    cudaGetSymbolAddress((void**)&wf2, g_wf2);
    cudaGetSymbolAddress((void**)&wf3, g_wf3);
    __nv_bfloat16 *h1, *l1, *h2, *l2;
    cudaGetSymbolAddress((void**)&h1, g_h1);
    cudaGetSymbolAddress((void**)&l1, g_l1);
    cudaGetSymbolAddress((void**)&h2, g_h2);
    cudaGetSymbolAddress((void**)&l2, g_l2);

    init_table_kernel<<<4096, 256>>>();
    scatter_kernel<<<(Nq + 255) / 256, 256>>>(coords);
    prep_w_kernel<<<(Kq * 2048 + 255) / 256, 256>>>(w2, wf2);
    prep_w_kernel<<<(Kq * 2048 + 255) / 256, 256>>>(w3, wf3);
    build_nbr_kernel<<<(Nq + 255) / 256, 256>>>(coords);

    layer1_kernel<<<Nq / 128, 256>>>(feats, w1, b1, g1, be1, m1, v1, h1, l1);
    conv_mma_kernel<<<Nq / 128, 256, SM_TOT>>>(h1, l1, wf2, b2, g2, be2, m2, v2,
                                               nullptr, h2, l2, 1);
    conv_mma_kernel<<<Nq / 128, 256, SM_TOT>>>(h2, l2, wf3, b3, g3, be3, m3, v3,
                                               out, nullptr, nullptr, 0);
}